// round 3
// baseline (speedup 1.0000x reference)
#include <cuda_runtime.h>
#include <cstdint>

#define B_TOTAL   4096
#define Z_TILE    32
#define NBLOCKS   (B_TOTAL / Z_TILE)   // 128
#define FEAT      832                  // 64*(1+3+9)
#define SROW      833                  // padded smem row
#define NPATH     15
#define KTOT      4096                 // (a,b) pairs
#define WROW      (NPATH * 64)         // 960 floats per k
#define WT_ELEMS  (KTOT * WROW)
#define OFF1      64
#define OFF2      256

// Transposed weights W_t[k][path][c]  (~15.7 MB device scratch)
__device__ float g_Wt[WT_ELEMS];

__global__ void wt_transpose_kernel(const float* __restrict__ w) {
    int o = blockIdx.x * 256 + threadIdx.x;
    if (o >= WT_ELEMS) return;
    int k = o / WROW;
    int r = o - k * WROW;       // p*64 + c
    int p = r >> 6;
    int c = r & 63;
    g_Wt[o] = w[p * 262144 + c * 4096 + k];
}

#define FMA2(acc, a, b) asm("fma.rn.f32x2 %0, %1, %2, %0;" : "+l"(acc) : "l"(a), "l"(b))

__device__ __forceinline__ unsigned long long dup2(float p) {
    unsigned long long d;
    unsigned int u = __float_as_uint(p);
    asm("mov.b64 %0, {%1, %2};" : "=l"(d) : "r"(u), "r"(u));
    return d;
}

__device__ __forceinline__ float2 unpk(unsigned long long v) {
    unsigned int lo, hi;
    asm("mov.b64 {%0, %1}, %2;" : "=r"(lo), "=r"(hi) : "l"(v));
    return make_float2(__uint_as_float(lo), __uint_as_float(hi));
}

template <int DIM>
__device__ __forceinline__ void do_path(const float* __restrict__ swc, const int pidx,
                                        const int w8,
                                        unsigned long long (*acc)[DIM],
                                        const float* __restrict__ P) {
    const ulonglong2* wp = reinterpret_cast<const ulonglong2*>(swc + pidx * 64 + w8);
    ulonglong2 wa = wp[0];   // c pairs (0,1),(2,3)
    ulonglong2 wb = wp[1];   // c pairs (4,5),(6,7)
#pragma unroll
    for (int u = 0; u < DIM; u++) {
        unsigned long long pd = dup2(P[u]);
        FMA2(acc[0][u], wa.x, pd);
        FMA2(acc[1][u], wa.y, pd);
        FMA2(acc[2][u], wb.x, pd);
        FMA2(acc[3][u], wb.y, pd);
    }
}

__global__ void __launch_bounds__(256, 1)
tp_kernel(const float* __restrict__ x1, const float* __restrict__ x2,
          float* __restrict__ out) {
    extern __shared__ float smem[];
    float* sA  = smem;                          // 32*833
    float* sB  = smem + Z_TILE * SROW;          // 32*833
    float* sW0 = smem + 2 * Z_TILE * SROW;      // 960
    float* sW1 = sW0 + WROW;                    // 960

    const int tid  = threadIdx.x;
    const int w8   = (tid >> 5) * 8;   // warp -> 8 output channels
    const int lane = tid & 31;         // lane -> z within tile
    const int z0   = blockIdx.x * Z_TILE;

    for (int r = 0; r < Z_TILE; r++) {
        const float* pa = x1 + (size_t)(z0 + r) * FEAT;
        const float* pb = x2 + (size_t)(z0 + r) * FEAT;
        for (int f = tid; f < FEAT; f += 256) {
            sA[r * SROW + f] = pa[f];
            sB[r * SROW + f] = pb[f];
        }
    }
    if (tid < 240) {
        float4 v = *reinterpret_cast<const float4*>(g_Wt + tid * 4);
        *reinterpret_cast<float4*>(sW0 + tid * 4) = v;
    }
    __syncthreads();

    const float* Az = sA + lane * SROW;
    const float* Bz = sB + lane * SROW;

    unsigned long long acc2[4][9], acc1[4][3], acc0[4][1];
#pragma unroll
    for (int j = 0; j < 4; j++) {
        acc0[j][0] = 0ull;
#pragma unroll
        for (int u = 0; u < 3; u++) acc1[j][u] = 0ull;
#pragma unroll
        for (int u = 0; u < 9; u++) acc2[j][u] = 0ull;
    }

    float* swc = sW0;
    float* swn = sW1;

#pragma unroll 1
    for (int a = 0; a < 64; a++) {
        const float aS = Az[a];
        float av[3], am[9];
#pragma unroll
        for (int i = 0; i < 3; i++) av[i] = Az[OFF1 + a * 3 + i];
#pragma unroll
        for (int i = 0; i < 9; i++) am[i] = Az[OFF2 + a * 9 + i];

#pragma unroll 1
        for (int b = 0; b < 64; b++) {
            const int k = a * 64 + b;
            const bool pre = (tid < 240) && (k + 1 < KTOT);
            float4 pf;
            if (pre) pf = *reinterpret_cast<const float4*>(g_Wt + (size_t)(k + 1) * WROW + tid * 4);

            const float bS = Bz[b];
            float bv[3], bm[9];
#pragma unroll
            for (int i = 0; i < 3; i++) bv[i] = Bz[OFF1 + b * 3 + i];
#pragma unroll
            for (int i = 0; i < 9; i++) bm[i] = Bz[OFF2 + b * 9 + i];

            float P[9];

            // p0: (0,0)->0
            P[0] = aS * bS;
            do_path<1>(swc, 0, w8, acc0, P);
            // p1: (0,1)->1
            P[0] = aS * bv[0]; P[1] = aS * bv[1]; P[2] = aS * bv[2];
            do_path<3>(swc, 1, w8, acc1, P);
            // p2: (0,2)->2
#pragma unroll
            for (int i = 0; i < 9; i++) P[i] = aS * bm[i];
            do_path<9>(swc, 2, w8, acc2, P);
            // p3: (1,0)->1
            P[0] = av[0] * bS; P[1] = av[1] * bS; P[2] = av[2] * bS;
            do_path<3>(swc, 3, w8, acc1, P);
            // p4: (1,1)->2 outer, u=3i+j
#pragma unroll
            for (int i = 0; i < 3; i++)
#pragma unroll
                for (int j = 0; j < 3; j++) P[3 * i + j] = av[i] * bv[j];
            do_path<9>(swc, 4, w8, acc2, P);
            // p5: (1,1)->0 dot
            P[0] = fmaf(av[2], bv[2], fmaf(av[1], bv[1], av[0] * bv[0]));
            do_path<1>(swc, 5, w8, acc0, P);
            // p6: (1,1)->1 cross
            P[0] = av[1] * bv[2] - av[2] * bv[1];
            P[1] = av[2] * bv[0] - av[0] * bv[2];
            P[2] = av[0] * bv[1] - av[1] * bv[0];
            do_path<3>(swc, 6, w8, acc1, P);
            // p7: (1,2)->1 k=1: P[e]=dot(av, bm_row_e)
#pragma unroll
            for (int e = 0; e < 3; e++)
                P[e] = fmaf(av[2], bm[3 * e + 2], fmaf(av[1], bm[3 * e + 1], av[0] * bm[3 * e]));
            do_path<3>(swc, 7, w8, acc1, P);
            // p8: (1,2)->2 eps: P[3e+g]=cross(av, bm_row_e)[g]
#pragma unroll
            for (int e = 0; e < 3; e++) {
                P[3 * e + 0] = av[1] * bm[3 * e + 2] - av[2] * bm[3 * e + 1];
                P[3 * e + 1] = av[2] * bm[3 * e + 0] - av[0] * bm[3 * e + 2];
                P[3 * e + 2] = av[0] * bm[3 * e + 1] - av[1] * bm[3 * e + 0];
            }
            do_path<9>(swc, 8, w8, acc2, P);
            // p9: (2,0)->2
#pragma unroll
            for (int i = 0; i < 9; i++) P[i] = am[i] * bS;
            do_path<9>(swc, 9, w8, acc2, P);
            // p10: (2,1)->1 k=1: P[d]=dot(am_row_d, bv)
#pragma unroll
            for (int d = 0; d < 3; d++)
                P[d] = fmaf(am[3 * d + 2], bv[2], fmaf(am[3 * d + 1], bv[1], am[3 * d] * bv[0]));
            do_path<3>(swc, 10, w8, acc1, P);
            // p11: (2,1)->2 eps: P[3d+g]=cross(am_row_d, bv)[g]
#pragma unroll
            for (int d = 0; d < 3; d++) {
                P[3 * d + 0] = am[3 * d + 1] * bv[2] - am[3 * d + 2] * bv[1];
                P[3 * d + 1] = am[3 * d + 2] * bv[0] - am[3 * d + 0] * bv[2];
                P[3 * d + 2] = am[3 * d + 0] * bv[1] - am[3 * d + 1] * bv[0];
            }
            do_path<9>(swc, 11, w8, acc2, P);
            // M[d][f] = dot(am_row_d, bm_row_f) shared by p12,p13,p14
            float M[9];
#pragma unroll
            for (int d = 0; d < 3; d++)
#pragma unroll
                for (int f = 0; f < 3; f++)
                    M[3 * d + f] = fmaf(am[3 * d + 2], bm[3 * f + 2],
                                   fmaf(am[3 * d + 1], bm[3 * f + 1],
                                        am[3 * d] * bm[3 * f]));
            // p12: (2,2)->2 k=1
            do_path<9>(swc, 12, w8, acc2, M);
            // p13: (2,2)->0 k=2 (Frobenius = trace(M))
            P[0] = M[0] + M[4] + M[8];
            do_path<1>(swc, 13, w8, acc0, P);
            // p14: (2,2)->1 eps k=1
            P[0] = M[5] - M[7];
            P[1] = M[6] - M[2];
            P[2] = M[1] - M[3];
            do_path<3>(swc, 14, w8, acc1, P);

            if (pre) *reinterpret_cast<float4*>(swn + tid * 4) = pf;
            __syncthreads();
            float* t = swc; swc = swn; swn = t;
        }
    }

    const int zg = z0 + lane;
    float* po = out + (size_t)zg * FEAT;
#pragma unroll
    for (int j = 0; j < 4; j++) {
        const int c0 = w8 + 2 * j;
        float2 f0 = unpk(acc0[j][0]);
        po[c0] = f0.x;
        po[c0 + 1] = f0.y;
#pragma unroll
        for (int u = 0; u < 3; u++) {
            float2 f = unpk(acc1[j][u]);
            po[OFF1 + c0 * 3 + u] = f.x;
            po[OFF1 + (c0 + 1) * 3 + u] = f.y;
        }
#pragma unroll
        for (int u = 0; u < 9; u++) {
            float2 f = unpk(acc2[j][u]);
            po[OFF2 + c0 * 9 + u] = f.x;
            po[OFF2 + (c0 + 1) * 9 + u] = f.y;
        }
    }
}

extern "C" void kernel_launch(void* const* d_in, const int* in_sizes, int n_in,
                              void* d_out, int out_size) {
    const float* x1 = (const float*)d_in[0];
    const float* x2 = (const float*)d_in[1];
    const float* w  = (const float*)d_in[2];
    float* out = (float*)d_out;

    // 1) transpose weights into k-major scratch
    wt_transpose_kernel<<<(WT_ELEMS + 255) / 256, 256>>>(w);

    // 2) main tensor-product kernel
    const int smem_bytes = (2 * Z_TILE * SROW + 2 * WROW) * (int)sizeof(float);
    static int attr_set = 0;
    if (!attr_set) {
        cudaFuncSetAttribute(tp_kernel, cudaFuncAttributeMaxDynamicSharedMemorySize, smem_bytes);
        attr_set = 1;
    }
    tp_kernel<<<NBLOCKS, 256, smem_bytes>>>(x1, x2, out);
}